// round 3
// baseline (speedup 1.0000x reference)
#include <cuda_runtime.h>
#include <cuda_bf16.h>
#include <math.h>

#define NN 100000
#define EE 3200000
#define DD 128
#define H2 256
#define LL 4
#define GG 1000
#define CC 10
#define BN_EPS 1e-5f
#define NPART 98   // ceil(NN/1024)

// -------- scratch --------
__device__ float d_agg[(size_t)NN * DD];
__device__ float d_y1 [(size_t)NN * H2];
__device__ float d_y2 [(size_t)NN * DD];
__device__ float d_h  [(size_t)NN * DD];
__device__ float d_ge [(size_t)GG * DD];
__device__ float d_gm1[(size_t)GG * DD];
__device__ float d_stats[2 * H2];
__device__ float d_scale[H2];
__device__ float d_shift[H2];
// CSR scratch
__device__ int d_counts[NN];
__device__ int d_off[NN + 1];
__device__ int d_cur[NN];
__device__ int d_csr[EE];
__device__ int d_part[NPART];

// ================= CSR build =================
__global__ void hist_kernel(const int* __restrict__ dst) {
    int e = blockIdx.x * blockDim.x + threadIdx.x;
    if (e < EE) atomicAdd(&d_counts[dst[e]], 1);
}

// block-local inclusive scan of counts -> d_off[i+1]; block totals -> d_part
__global__ void scan_block_kernel() {
    __shared__ int sm[1024];
    int b = blockIdx.x, t = threadIdx.x;
    int i = b * 1024 + t;
    sm[t] = (i < NN) ? d_counts[i] : 0;
    __syncthreads();
    for (int s = 1; s < 1024; s <<= 1) {
        int a = (t >= s) ? sm[t - s] : 0;
        __syncthreads();
        sm[t] += a;
        __syncthreads();
    }
    if (i < NN) d_off[i + 1] = sm[t];
    if (t == 1023) d_part[b] = sm[1023];
}

// inclusive scan of the NPART block totals (single small block)
__global__ void scan_part_kernel() {
    __shared__ int sm[128];
    int t = threadIdx.x;
    sm[t] = (t < NPART) ? d_part[t] : 0;
    __syncthreads();
    for (int s = 1; s < 128; s <<= 1) {
        int a = (t >= s) ? sm[t - s] : 0;
        __syncthreads();
        sm[t] += a;
        __syncthreads();
    }
    if (t < NPART) d_part[t] = sm[t];
    if (t == 0) { d_off[0] = 0; d_cur[0] = 0; }
}

// add carries, produce final d_off and d_cur
__global__ void scan_add_kernel() {
    int b = blockIdx.x, t = threadIdx.x;
    int i = b * 1024 + t;
    if (i < NN) {
        int add = (b > 0) ? d_part[b - 1] : 0;
        int v = d_off[i + 1] + add;
        d_off[i + 1] = v;
        if (i + 1 < NN) d_cur[i + 1] = v;
    }
}

__global__ void fill_kernel(const int* __restrict__ src, const int* __restrict__ dst) {
    int e = blockIdx.x * blockDim.x + threadIdx.x;
    if (e < EE) {
        int d = dst[e];
        int p = atomicAdd(&d_cur[d], 1);
        d_csr[p] = src[e];
    }
}

// ================= aggregation: z[n] = (1+eps)*h[n] + sum_neigh h[s] =================
__global__ void aggregate_kernel(const float* __restrict__ h,
                                 const float* __restrict__ epsp) {
    int gt = blockIdx.x * blockDim.x + threadIdx.x;
    int n = gt >> 5;
    int lane = gt & 31;
    if (n >= NN) return;
    int beg = d_off[n], end = d_off[n + 1];
    float4 acc = make_float4(0.f, 0.f, 0.f, 0.f);
    const float* hl = h + (size_t)lane * 4;
    int i = beg;
    for (; i + 4 <= end; i += 4) {
        int s0 = d_csr[i], s1 = d_csr[i + 1], s2 = d_csr[i + 2], s3 = d_csr[i + 3];
        float4 v0 = *reinterpret_cast<const float4*>(hl + (size_t)s0 * DD);
        float4 v1 = *reinterpret_cast<const float4*>(hl + (size_t)s1 * DD);
        float4 v2 = *reinterpret_cast<const float4*>(hl + (size_t)s2 * DD);
        float4 v3 = *reinterpret_cast<const float4*>(hl + (size_t)s3 * DD);
        acc.x += (v0.x + v1.x) + (v2.x + v3.x);
        acc.y += (v0.y + v1.y) + (v2.y + v3.y);
        acc.z += (v0.z + v1.z) + (v2.z + v3.z);
        acc.w += (v0.w + v1.w) + (v2.w + v3.w);
    }
    for (; i < end; i++) {
        int s0 = d_csr[i];
        float4 v0 = *reinterpret_cast<const float4*>(hl + (size_t)s0 * DD);
        acc.x += v0.x; acc.y += v0.y; acc.z += v0.z; acc.w += v0.w;
    }
    float e = 1.0f + epsp[0];
    float4 self = *reinterpret_cast<const float4*>(hl + (size_t)n * DD);
    acc.x += e * self.x; acc.y += e * self.y;
    acc.z += e * self.z; acc.w += e * self.w;
    *reinterpret_cast<float4*>(d_agg + (size_t)n * DD + lane * 4) = acc;
}

// ================= pool =================
__global__ void pool_kernel(const float* __restrict__ h,
                            const int* __restrict__ batch) {
    int gt = blockIdx.x * blockDim.x + threadIdx.x;
    int n = gt >> 5;
    int lane = gt & 31;
    if (n >= NN) return;
    int g = batch[n];
    float4 v = *reinterpret_cast<const float4*>(h + (size_t)n * DD + lane * 4);
    atomicAdd(reinterpret_cast<float4*>(d_ge + (size_t)g * DD + lane * 4), v);
}

// ================= 128x128 SGEMM with FFMA2 (fma.rn.f32x2) inner loop ==================
// A-tile stored DUPLICATED in smem: As2[k][2m]=As2[k][2m+1]=a(m,k)  -> LDS.128 yields
// (a,a,b,b) = two ready-made f32x2 broadcast operands. B natural pairs. 32 FFMA2/k-step.
// MODE 1: a = relu(A*d_scale[k]+d_shift[k]);  MODE 2: a = A
template <int K, int NC, int MODE>
__global__ __launch_bounds__(256, 2) void gemm128_kernel(
    const float* __restrict__ A,
    const float* __restrict__ W,
    const float* __restrict__ bias,
    float* __restrict__ C, int M)
{
    constexpr int BM = 128, BN = 128, BK = 16;
    constexpr int KT = K / BK;
    __shared__ float As2[2][BK][2 * BM + 4];
    __shared__ float Bs[2][BK][BN];
    __shared__ float s_sum[BN];
    __shared__ float s_sq[BN];

    int tid = threadIdx.x;
    int tr = tid >> 4;       // 0..15
    int tc = tid & 15;       // 0..15
    int rowBase = blockIdx.x * BM;
    int colBase = blockIdx.y * BN;

    unsigned long long acc[8][4];
#pragma unroll
    for (int i = 0; i < 8; i++)
#pragma unroll
        for (int j = 0; j < 4; j++) acc[i][j] = 0ull;

    float4 a_reg[2], b_reg[2];

    auto loadA = [&](int k0, int q) -> float4 {
        int fIdx = tid + q * 256;
        int m = fIdx >> 2;
        int kq = (fIdx & 3) << 2;
        int gr = rowBase + m;
        float4 v = make_float4(0.f, 0.f, 0.f, 0.f);
        if (gr < M) {
            size_t g = (size_t)gr * K + k0 + kq;
            float4 a = *reinterpret_cast<const float4*>(A + g);
            if (MODE == 1) {
                int kc = k0 + kq;
                v.x = fmaxf(a.x * d_scale[kc + 0] + d_shift[kc + 0], 0.f);
                v.y = fmaxf(a.y * d_scale[kc + 1] + d_shift[kc + 1], 0.f);
                v.z = fmaxf(a.z * d_scale[kc + 2] + d_shift[kc + 2], 0.f);
                v.w = fmaxf(a.w * d_scale[kc + 3] + d_shift[kc + 3], 0.f);
            } else {
                v = a;
            }
        }
        return v;
    };
    auto loadB = [&](int k0, int q) -> float4 {
        int fIdx = tid + q * 256;
        int kk = fIdx >> 5;
        int n4 = (fIdx & 31) << 2;
        return *reinterpret_cast<const float4*>(W + (size_t)(k0 + kk) * NC + colBase + n4);
    };
    auto storeA = [&](int buf, int q, float4 v) {
        int fIdx = tid + q * 256;
        int m = fIdx >> 2;
        int kq = (fIdx & 3) << 2;
        *reinterpret_cast<float2*>(&As2[buf][kq + 0][2 * m]) = make_float2(v.x, v.x);
        *reinterpret_cast<float2*>(&As2[buf][kq + 1][2 * m]) = make_float2(v.y, v.y);
        *reinterpret_cast<float2*>(&As2[buf][kq + 2][2 * m]) = make_float2(v.z, v.z);
        *reinterpret_cast<float2*>(&As2[buf][kq + 3][2 * m]) = make_float2(v.w, v.w);
    };
    auto storeB = [&](int buf, int q, float4 v) {
        int fIdx = tid + q * 256;
        int kk = fIdx >> 5;
        int n4 = (fIdx & 31) << 2;
        *reinterpret_cast<float4*>(&Bs[buf][kk][n4]) = v;
    };

    a_reg[0] = loadA(0, 0); a_reg[1] = loadA(0, 1);
    b_reg[0] = loadB(0, 0); b_reg[1] = loadB(0, 1);
    storeA(0, 0, a_reg[0]); storeA(0, 1, a_reg[1]);
    storeB(0, 0, b_reg[0]); storeB(0, 1, b_reg[1]);
    __syncthreads();

    for (int kt = 0; kt < KT; kt++) {
        int buf = kt & 1;
        if (kt + 1 < KT) {
            int k0 = (kt + 1) * BK;
            a_reg[0] = loadA(k0, 0); a_reg[1] = loadA(k0, 1);
            b_reg[0] = loadB(k0, 0); b_reg[1] = loadB(k0, 1);
        }
#pragma unroll
        for (int kk = 0; kk < BK; kk++) {
            const ulonglong2* ar = reinterpret_cast<const ulonglong2*>(&As2[buf][kk][tr * 16]);
            ulonglong2 u0 = ar[0], u1 = ar[1], u2 = ar[2], u3 = ar[3];
            unsigned long long aD[8] = {u0.x, u0.y, u1.x, u1.y, u2.x, u2.y, u3.x, u3.y};
            const ulonglong2* br = reinterpret_cast<const ulonglong2*>(&Bs[buf][kk][tc * 8]);
            ulonglong2 v0 = br[0], v1 = br[1];
            unsigned long long bP[4] = {v0.x, v0.y, v1.x, v1.y};
#pragma unroll
            for (int i = 0; i < 8; i++)
#pragma unroll
                for (int jp = 0; jp < 4; jp++)
                    asm("fma.rn.f32x2 %0, %1, %2, %0;"
                        : "+l"(acc[i][jp]) : "l"(aD[i]), "l"(bP[jp]));
        }
        if (kt + 1 < KT) {
            storeA(buf ^ 1, 0, a_reg[0]); storeA(buf ^ 1, 1, a_reg[1]);
            storeB(buf ^ 1, 0, b_reg[0]); storeB(buf ^ 1, 1, b_reg[1]);
        }
        __syncthreads();
    }

    // epilogue: bias add, store, fused column stats
    float bj[8];
#pragma unroll
    for (int j = 0; j < 8; j++) bj[j] = bias[colBase + tc * 8 + j];

    float csum[8], csq[8];
#pragma unroll
    for (int j = 0; j < 8; j++) { csum[j] = 0.f; csq[j] = 0.f; }

#pragma unroll
    for (int i = 0; i < 8; i++) {
        int gr = rowBase + tr * 8 + i;
        if (gr < M) {
            float y[8];
#pragma unroll
            for (int jp = 0; jp < 4; jp++) {
                unsigned long long u = acc[i][jp];
                y[2 * jp]     = __uint_as_float((unsigned)(u & 0xffffffffull)) + bj[2 * jp];
                y[2 * jp + 1] = __uint_as_float((unsigned)(u >> 32))           + bj[2 * jp + 1];
            }
#pragma unroll
            for (int j = 0; j < 8; j++) {
                csum[j] += y[j];
                csq[j] += y[j] * y[j];
            }
            size_t base = (size_t)gr * NC + colBase + tc * 8;
            *reinterpret_cast<float4*>(C + base)     = *reinterpret_cast<float4*>(y);
            *reinterpret_cast<float4*>(C + base + 4) = *reinterpret_cast<float4*>(y + 4);
        }
    }

    if (tid < BN) { s_sum[tid] = 0.f; s_sq[tid] = 0.f; }
    __syncthreads();
#pragma unroll
    for (int j = 0; j < 8; j++) {
        atomicAdd(&s_sum[tc * 8 + j], csum[j]);
        atomicAdd(&s_sq[tc * 8 + j], csq[j]);
    }
    __syncthreads();
    if (tid < BN) {
        atomicAdd(&d_stats[colBase + tid], s_sum[tid]);
        atomicAdd(&d_stats[NC + colBase + tid], s_sq[tid]);
    }
}

// ================= BN finalize =================
__global__ void finalize_kernel(const float* __restrict__ g,
                                const float* __restrict__ bt, int M, int NC) {
    int c = threadIdx.x;
    if (c < NC) {
        float invM = 1.0f / (float)M;
        float mean = d_stats[c] * invM;
        float var  = d_stats[NC + c] * invM - mean * mean;
        float sc   = g[c] * rsqrtf(var + BN_EPS);
        d_scale[c] = sc;
        d_shift[c] = bt[c] - mean * sc;
    }
}

// ================= h = relu(y*scale+shift) =================
__global__ void apply_bn_relu_kernel(const float* __restrict__ y,
                                     float* __restrict__ h, int M) {
    int idx = blockIdx.x * blockDim.x + threadIdx.x;
    int total = M * (DD / 4);
    if (idx >= total) return;
    int c4 = (idx % (DD / 4)) * 4;
    float4 v = reinterpret_cast<const float4*>(y)[idx];
    float4 o;
    float t;
    t = v.x * d_scale[c4 + 0] + d_shift[c4 + 0]; o.x = t > 0.f ? t : 0.f;
    t = v.y * d_scale[c4 + 1] + d_shift[c4 + 1]; o.y = t > 0.f ? t : 0.f;
    t = v.z * d_scale[c4 + 2] + d_shift[c4 + 2]; o.z = t > 0.f ? t : 0.f;
    t = v.w * d_scale[c4 + 3] + d_shift[c4 + 3]; o.w = t > 0.f ? t : 0.f;
    reinterpret_cast<float4*>(h)[idx] = o;
}

// ================= head =================
__global__ void head_kernel(const float* __restrict__ gm1,
                            const float* __restrict__ Wm2,
                            const float* __restrict__ bm2,
                            float* __restrict__ out) {
    __shared__ float sh[DD];
    int r = blockIdx.x;
    int t = threadIdx.x;
    float v = gm1[(size_t)r * DD + t] * d_scale[t] + d_shift[t];
    sh[t] = v > 0.f ? v : 0.f;
    __syncthreads();
    if (t < CC) {
        float acc = bm2[t];
#pragma unroll 16
        for (int k = 0; k < DD; k++) acc += sh[k] * Wm2[k * CC + t];
        out[(size_t)r * CC + t] = acc;
    }
}

extern "C" void kernel_launch(void* const* d_in, const int* in_sizes, int n_in,
                              void* d_out, int out_size) {
    const float* x    = (const float*)d_in[0];
    const int*   ei   = (const int*)d_in[1];
    const int*   batch= (const int*)d_in[2];
    const float* eps  = (const float*)d_in[3];
    const float* W1   = (const float*)d_in[4];
    const float* b1   = (const float*)d_in[5];
    const float* g1   = (const float*)d_in[6];
    const float* bt1  = (const float*)d_in[7];
    const float* W2   = (const float*)d_in[8];
    const float* b2   = (const float*)d_in[9];
    const float* g2   = (const float*)d_in[10];
    const float* bt2  = (const float*)d_in[11];
    const float* Wm1  = (const float*)d_in[12];
    const float* bm1  = (const float*)d_in[13];
    const float* gm   = (const float*)d_in[14];
    const float* btm  = (const float*)d_in[15];
    const float* Wm2  = (const float*)d_in[16];
    const float* bm2  = (const float*)d_in[17];
    float* out = (float*)d_out;

    const int* src = ei;
    const int* dst = ei + EE;

    void *countsPtr, *statsPtr, *gePtr;
    cudaGetSymbolAddress(&countsPtr, d_counts);
    cudaGetSymbolAddress(&statsPtr,  d_stats);
    cudaGetSymbolAddress(&gePtr,     d_ge);

    float *aggPtr, *hPtr, *y1Ptr, *y2Ptr, *gm1Ptr;
    cudaGetSymbolAddress((void**)&aggPtr, d_agg);
    cudaGetSymbolAddress((void**)&hPtr,   d_h);
    cudaGetSymbolAddress((void**)&y1Ptr,  d_y1);
    cudaGetSymbolAddress((void**)&y2Ptr,  d_y2);
    cudaGetSymbolAddress((void**)&gm1Ptr, d_gm1);

    // ---- CSR build (edges are layer-invariant) ----
    cudaMemsetAsync(countsPtr, 0, NN * sizeof(int));
    hist_kernel<<<(EE + 255) / 256, 256>>>(dst);
    scan_block_kernel<<<NPART, 1024>>>();
    scan_part_kernel<<<1, 128>>>();
    scan_add_kernel<<<NPART, 1024>>>();
    fill_kernel<<<(EE + 255) / 256, 256>>>(src, dst);

    const int aggBlocks   = (NN * 32 + 255) / 256;
    const int poolBlocks  = (NN * 32 + 255) / 256;
    const int applyBlocks = (NN * (DD / 4) + 255) / 256;

    dim3 gemm1_grid((NN + 127) / 128, H2 / 128);
    dim3 gemm2_grid((NN + 127) / 128, DD / 128);
    dim3 gemmM_grid((GG + 127) / 128, DD / 128);

    for (int l = 0; l < LL; l++) {
        const float* hin = (l == 0) ? x : (const float*)hPtr;

        aggregate_kernel<<<aggBlocks, 256>>>(hin, eps + l);

        cudaMemsetAsync(statsPtr, 0, 2 * H2 * sizeof(float));
        gemm128_kernel<DD, H2, 2><<<gemm1_grid, 256>>>(
            aggPtr, W1 + (size_t)l * DD * H2, b1 + (size_t)l * H2, y1Ptr, NN);
        finalize_kernel<<<1, H2>>>(g1 + (size_t)l * H2, bt1 + (size_t)l * H2, NN, H2);

        cudaMemsetAsync(statsPtr, 0, 2 * H2 * sizeof(float));
        gemm128_kernel<H2, DD, 1><<<gemm2_grid, 256>>>(
            y1Ptr, W2 + (size_t)l * H2 * DD, b2 + (size_t)l * DD, y2Ptr, NN);
        finalize_kernel<<<1, DD>>>(g2 + (size_t)l * DD, bt2 + (size_t)l * DD, NN, DD);

        apply_bn_relu_kernel<<<applyBlocks, 256>>>(y2Ptr, hPtr, NN);
    }

    cudaMemsetAsync(gePtr, 0, (size_t)GG * DD * sizeof(float));
    pool_kernel<<<poolBlocks, 256>>>(hPtr, batch);

    cudaMemsetAsync(statsPtr, 0, 2 * H2 * sizeof(float));
    gemm128_kernel<DD, DD, 2><<<gemmM_grid, 256>>>(
        (const float*)gePtr, Wm1, bm1, gm1Ptr, GG);
    finalize_kernel<<<1, DD>>>(gm, btm, GG, DD);

    head_kernel<<<GG, DD>>>(gm1Ptr, Wm2, bm2, out);
}

// round 4
// speedup vs baseline: 1.0994x; 1.0994x over previous
#include <cuda_runtime.h>
#include <cuda_bf16.h>
#include <math.h>

#define NN 100000
#define EE 3200000
#define DD 128
#define H2 256
#define LL 4
#define GG 1000
#define CC 10
#define BN_EPS 1e-5f
#define NPART 98   // ceil(NN/1024)

// -------- scratch --------
__device__ float d_agg[(size_t)NN * DD];
__device__ float d_y1 [(size_t)NN * H2];
__device__ float d_y2 [(size_t)NN * DD];
__device__ float d_h  [(size_t)NN * DD];
__device__ float d_ge [(size_t)GG * DD];
__device__ float d_gm1[(size_t)GG * DD];
__device__ float d_stats[2 * H2];
__device__ float d_scale[H2];
__device__ float d_shift[H2];
// CSR scratch
__device__ int d_counts[NN];
__device__ int d_off[NN + 1];
__device__ int d_cur[NN];
__device__ int d_csr[EE];
__device__ int d_part[NPART];

// ================= CSR build =================
__global__ void hist_kernel(const int* __restrict__ dst) {
    int e = blockIdx.x * blockDim.x + threadIdx.x;
    if (e < EE) atomicAdd(&d_counts[dst[e]], 1);
}

__global__ void scan_block_kernel() {
    __shared__ int sm[1024];
    int b = blockIdx.x, t = threadIdx.x;
    int i = b * 1024 + t;
    sm[t] = (i < NN) ? d_counts[i] : 0;
    __syncthreads();
    for (int s = 1; s < 1024; s <<= 1) {
        int a = (t >= s) ? sm[t - s] : 0;
        __syncthreads();
        sm[t] += a;
        __syncthreads();
    }
    if (i < NN) d_off[i + 1] = sm[t];
    if (t == 1023) d_part[b] = sm[1023];
}

__global__ void scan_part_kernel() {
    __shared__ int sm[128];
    int t = threadIdx.x;
    sm[t] = (t < NPART) ? d_part[t] : 0;
    __syncthreads();
    for (int s = 1; s < 128; s <<= 1) {
        int a = (t >= s) ? sm[t - s] : 0;
        __syncthreads();
        sm[t] += a;
        __syncthreads();
    }
    if (t < NPART) d_part[t] = sm[t];
    if (t == 0) { d_off[0] = 0; d_cur[0] = 0; }
}

__global__ void scan_add_kernel() {
    int b = blockIdx.x, t = threadIdx.x;
    int i = b * 1024 + t;
    if (i < NN) {
        int add = (b > 0) ? d_part[b - 1] : 0;
        int v = d_off[i + 1] + add;
        d_off[i + 1] = v;
        if (i + 1 < NN) d_cur[i + 1] = v;
    }
}

__global__ void fill_kernel(const int* __restrict__ src, const int* __restrict__ dst) {
    int e = blockIdx.x * blockDim.x + threadIdx.x;
    if (e < EE) {
        int d = dst[e];
        int p = atomicAdd(&d_cur[d], 1);
        d_csr[p] = src[e];
    }
}

// ================= aggregation =================
__global__ void aggregate_kernel(const float* __restrict__ h,
                                 const float* __restrict__ epsp) {
    int gt = blockIdx.x * blockDim.x + threadIdx.x;
    int n = gt >> 5;
    int lane = gt & 31;
    if (n >= NN) return;
    int beg = d_off[n], end = d_off[n + 1];
    float4 acc = make_float4(0.f, 0.f, 0.f, 0.f);
    const float* hl = h + (size_t)lane * 4;
    int i = beg;
    for (; i + 4 <= end; i += 4) {
        int s0 = d_csr[i], s1 = d_csr[i + 1], s2 = d_csr[i + 2], s3 = d_csr[i + 3];
        float4 v0 = *reinterpret_cast<const float4*>(hl + (size_t)s0 * DD);
        float4 v1 = *reinterpret_cast<const float4*>(hl + (size_t)s1 * DD);
        float4 v2 = *reinterpret_cast<const float4*>(hl + (size_t)s2 * DD);
        float4 v3 = *reinterpret_cast<const float4*>(hl + (size_t)s3 * DD);
        acc.x += (v0.x + v1.x) + (v2.x + v3.x);
        acc.y += (v0.y + v1.y) + (v2.y + v3.y);
        acc.z += (v0.z + v1.z) + (v2.z + v3.z);
        acc.w += (v0.w + v1.w) + (v2.w + v3.w);
    }
    for (; i < end; i++) {
        int s0 = d_csr[i];
        float4 v0 = *reinterpret_cast<const float4*>(hl + (size_t)s0 * DD);
        acc.x += v0.x; acc.y += v0.y; acc.z += v0.z; acc.w += v0.w;
    }
    float e = 1.0f + epsp[0];
    float4 self = *reinterpret_cast<const float4*>(hl + (size_t)n * DD);
    acc.x += e * self.x; acc.y += e * self.y;
    acc.z += e * self.z; acc.w += e * self.w;
    *reinterpret_cast<float4*>(d_agg + (size_t)n * DD + lane * 4) = acc;
}

// ================= pool =================
__global__ void pool_kernel(const float* __restrict__ h,
                            const int* __restrict__ batch) {
    int gt = blockIdx.x * blockDim.x + threadIdx.x;
    int n = gt >> 5;
    int lane = gt & 31;
    if (n >= NN) return;
    int g = batch[n];
    float4 v = *reinterpret_cast<const float4*>(h + (size_t)n * DD + lane * 4);
    atomicAdd(reinterpret_cast<float4*>(d_ge + (size_t)g * DD + lane * 4), v);
}

// ================= 128x128 SGEMM: FFMA2 with register-packed A broadcast ==============
// A in smem NORMAL layout (LDS stays 64B/thread/k). Per k-step: 8 scalar a's ->
// 8x mov.b64 (a,a) on ALU pipe; B read as natural f32x2 pairs; 32 FFMA2 on FMA pipe.
// MODE 1: a = relu(A*d_scale[k]+d_shift[k]);  MODE 2: a = A
template <int K, int NC, int MODE>
__global__ __launch_bounds__(256, 2) void gemm128_kernel(
    const float* __restrict__ A,
    const float* __restrict__ W,
    const float* __restrict__ bias,
    float* __restrict__ C, int M)
{
    constexpr int BM = 128, BN = 128, BK = 16;
    constexpr int KT = K / BK;
    __shared__ float As[2][BK][BM + 4];
    __shared__ float Bs[2][BK][BN];
    __shared__ float s_sum[BN];
    __shared__ float s_sq[BN];

    int tid = threadIdx.x;
    int tr = tid >> 4;       // 0..15
    int tc = tid & 15;       // 0..15
    int rowBase = blockIdx.x * BM;
    int colBase = blockIdx.y * BN;

    unsigned long long acc[8][4];
#pragma unroll
    for (int i = 0; i < 8; i++)
#pragma unroll
        for (int j = 0; j < 4; j++) acc[i][j] = 0ull;

    float4 a_reg[2], b_reg[2];

    auto loadA = [&](int k0, int q) -> float4 {
        int fIdx = tid + q * 256;
        int m = fIdx >> 2;
        int kq = (fIdx & 3) << 2;
        int gr = rowBase + m;
        float4 v = make_float4(0.f, 0.f, 0.f, 0.f);
        if (gr < M) {
            size_t g = (size_t)gr * K + k0 + kq;
            float4 a = *reinterpret_cast<const float4*>(A + g);
            if (MODE == 1) {
                int kc = k0 + kq;
                v.x = fmaxf(a.x * d_scale[kc + 0] + d_shift[kc + 0], 0.f);
                v.y = fmaxf(a.y * d_scale[kc + 1] + d_shift[kc + 1], 0.f);
                v.z = fmaxf(a.z * d_scale[kc + 2] + d_shift[kc + 2], 0.f);
                v.w = fmaxf(a.w * d_scale[kc + 3] + d_shift[kc + 3], 0.f);
            } else {
                v = a;
            }
        }
        return v;
    };
    auto loadB = [&](int k0, int q) -> float4 {
        int fIdx = tid + q * 256;
        int kk = fIdx >> 5;
        int n4 = (fIdx & 31) << 2;
        return *reinterpret_cast<const float4*>(W + (size_t)(k0 + kk) * NC + colBase + n4);
    };
    auto storeA = [&](int buf, int q, float4 v) {
        int fIdx = tid + q * 256;
        int m = fIdx >> 2;
        int kq = (fIdx & 3) << 2;
        As[buf][kq + 0][m] = v.x;
        As[buf][kq + 1][m] = v.y;
        As[buf][kq + 2][m] = v.z;
        As[buf][kq + 3][m] = v.w;
    };
    auto storeB = [&](int buf, int q, float4 v) {
        int fIdx = tid + q * 256;
        int kk = fIdx >> 5;
        int n4 = (fIdx & 31) << 2;
        *reinterpret_cast<float4*>(&Bs[buf][kk][n4]) = v;
    };

    a_reg[0] = loadA(0, 0); a_reg[1] = loadA(0, 1);
    b_reg[0] = loadB(0, 0); b_reg[1] = loadB(0, 1);
    storeA(0, 0, a_reg[0]); storeA(0, 1, a_reg[1]);
    storeB(0, 0, b_reg[0]); storeB(0, 1, b_reg[1]);
    __syncthreads();

    for (int kt = 0; kt < KT; kt++) {
        int buf = kt & 1;
        if (kt + 1 < KT) {
            int k0 = (kt + 1) * BK;
            a_reg[0] = loadA(k0, 0); a_reg[1] = loadA(k0, 1);
            b_reg[0] = loadB(k0, 0); b_reg[1] = loadB(k0, 1);
        }
#pragma unroll
        for (int kk = 0; kk < BK; kk++) {
            float ra[8];
            *reinterpret_cast<float4*>(ra)     = *reinterpret_cast<const float4*>(&As[buf][kk][tr * 8]);
            *reinterpret_cast<float4*>(ra + 4) = *reinterpret_cast<const float4*>(&As[buf][kk][tr * 8 + 4]);
            const ulonglong2* br = reinterpret_cast<const ulonglong2*>(&Bs[buf][kk][tc * 8]);
            ulonglong2 v0 = br[0], v1 = br[1];
            unsigned long long bP[4] = {v0.x, v0.y, v1.x, v1.y};
            unsigned long long aD[8];
#pragma unroll
            for (int i = 0; i < 8; i++)
                asm("mov.b64 %0, {%1, %1};" : "=l"(aD[i]) : "f"(ra[i]));
#pragma unroll
            for (int i = 0; i < 8; i++)
#pragma unroll
                for (int jp = 0; jp < 4; jp++)
                    asm("fma.rn.f32x2 %0, %1, %2, %0;"
                        : "+l"(acc[i][jp]) : "l"(aD[i]), "l"(bP[jp]));
        }
        if (kt + 1 < KT) {
            storeA(buf ^ 1, 0, a_reg[0]); storeA(buf ^ 1, 1, a_reg[1]);
            storeB(buf ^ 1, 0, b_reg[0]); storeB(buf ^ 1, 1, b_reg[1]);
        }
        __syncthreads();
    }

    // epilogue: bias add, store, fused column stats
    float bj[8];
#pragma unroll
    for (int j = 0; j < 8; j++) bj[j] = bias[colBase + tc * 8 + j];

    float csum[8], csq[8];
#pragma unroll
    for (int j = 0; j < 8; j++) { csum[j] = 0.f; csq[j] = 0.f; }

#pragma unroll
    for (int i = 0; i < 8; i++) {
        int gr = rowBase + tr * 8 + i;
        if (gr < M) {
            float y[8];
#pragma unroll
            for (int jp = 0; jp < 4; jp++) {
                unsigned long long u = acc[i][jp];
                y[2 * jp]     = __uint_as_float((unsigned)(u & 0xffffffffull)) + bj[2 * jp];
                y[2 * jp + 1] = __uint_as_float((unsigned)(u >> 32))           + bj[2 * jp + 1];
            }
#pragma unroll
            for (int j = 0; j < 8; j++) {
                csum[j] += y[j];
                csq[j] += y[j] * y[j];
            }
            size_t base = (size_t)gr * NC + colBase + tc * 8;
            *reinterpret_cast<float4*>(C + base)     = *reinterpret_cast<float4*>(y);
            *reinterpret_cast<float4*>(C + base + 4) = *reinterpret_cast<float4*>(y + 4);
        }
    }

    if (tid < BN) { s_sum[tid] = 0.f; s_sq[tid] = 0.f; }
    __syncthreads();
#pragma unroll
    for (int j = 0; j < 8; j++) {
        atomicAdd(&s_sum[tc * 8 + j], csum[j]);
        atomicAdd(&s_sq[tc * 8 + j], csq[j]);
    }
    __syncthreads();
    if (tid < BN) {
        atomicAdd(&d_stats[colBase + tid], s_sum[tid]);
        atomicAdd(&d_stats[NC + colBase + tid], s_sq[tid]);
    }
}

// ================= BN finalize =================
__global__ void finalize_kernel(const float* __restrict__ g,
                                const float* __restrict__ bt, int M, int NC) {
    int c = threadIdx.x;
    if (c < NC) {
        float invM = 1.0f / (float)M;
        float mean = d_stats[c] * invM;
        float var  = d_stats[NC + c] * invM - mean * mean;
        float sc   = g[c] * rsqrtf(var + BN_EPS);
        d_scale[c] = sc;
        d_shift[c] = bt[c] - mean * sc;
    }
}

// ================= h = relu(y*scale+shift) =================
__global__ void apply_bn_relu_kernel(const float* __restrict__ y,
                                     float* __restrict__ h, int M) {
    int idx = blockIdx.x * blockDim.x + threadIdx.x;
    int total = M * (DD / 4);
    if (idx >= total) return;
    int c4 = (idx % (DD / 4)) * 4;
    float4 v = reinterpret_cast<const float4*>(y)[idx];
    float4 o;
    float t;
    t = v.x * d_scale[c4 + 0] + d_shift[c4 + 0]; o.x = t > 0.f ? t : 0.f;
    t = v.y * d_scale[c4 + 1] + d_shift[c4 + 1]; o.y = t > 0.f ? t : 0.f;
    t = v.z * d_scale[c4 + 2] + d_shift[c4 + 2]; o.z = t > 0.f ? t : 0.f;
    t = v.w * d_scale[c4 + 3] + d_shift[c4 + 3]; o.w = t > 0.f ? t : 0.f;
    reinterpret_cast<float4*>(h)[idx] = o;
}

// ================= head =================
__global__ void head_kernel(const float* __restrict__ gm1,
                            const float* __restrict__ Wm2,
                            const float* __restrict__ bm2,
                            float* __restrict__ out) {
    __shared__ float sh[DD];
    int r = blockIdx.x;
    int t = threadIdx.x;
    float v = gm1[(size_t)r * DD + t] * d_scale[t] + d_shift[t];
    sh[t] = v > 0.f ? v : 0.f;
    __syncthreads();
    if (t < CC) {
        float acc = bm2[t];
#pragma unroll 16
        for (int k = 0; k < DD; k++) acc += sh[k] * Wm2[k * CC + t];
        out[(size_t)r * CC + t] = acc;
    }
}

extern "C" void kernel_launch(void* const* d_in, const int* in_sizes, int n_in,
                              void* d_out, int out_size) {
    const float* x    = (const float*)d_in[0];
    const int*   ei   = (const int*)d_in[1];
    const int*   batch= (const int*)d_in[2];
    const float* eps  = (const float*)d_in[3];
    const float* W1   = (const float*)d_in[4];
    const float* b1   = (const float*)d_in[5];
    const float* g1   = (const float*)d_in[6];
    const float* bt1  = (const float*)d_in[7];
    const float* W2   = (const float*)d_in[8];
    const float* b2   = (const float*)d_in[9];
    const float* g2   = (const float*)d_in[10];
    const float* bt2  = (const float*)d_in[11];
    const float* Wm1  = (const float*)d_in[12];
    const float* bm1  = (const float*)d_in[13];
    const float* gm   = (const float*)d_in[14];
    const float* btm  = (const float*)d_in[15];
    const float* Wm2  = (const float*)d_in[16];
    const float* bm2  = (const float*)d_in[17];
    float* out = (float*)d_out;

    const int* src = ei;
    const int* dst = ei + EE;

    void *countsPtr, *statsPtr, *gePtr;
    cudaGetSymbolAddress(&countsPtr, d_counts);
    cudaGetSymbolAddress(&statsPtr,  d_stats);
    cudaGetSymbolAddress(&gePtr,     d_ge);

    float *aggPtr, *hPtr, *y1Ptr, *y2Ptr, *gm1Ptr;
    cudaGetSymbolAddress((void**)&aggPtr, d_agg);
    cudaGetSymbolAddress((void**)&hPtr,   d_h);
    cudaGetSymbolAddress((void**)&y1Ptr,  d_y1);
    cudaGetSymbolAddress((void**)&y2Ptr,  d_y2);
    cudaGetSymbolAddress((void**)&gm1Ptr, d_gm1);

    // ---- CSR build ----
    cudaMemsetAsync(countsPtr, 0, NN * sizeof(int));
    hist_kernel<<<(EE + 255) / 256, 256>>>(dst);
    scan_block_kernel<<<NPART, 1024>>>();
    scan_part_kernel<<<1, 128>>>();
    scan_add_kernel<<<NPART, 1024>>>();
    fill_kernel<<<(EE + 255) / 256, 256>>>(src, dst);

    const int aggBlocks   = (NN * 32 + 255) / 256;
    const int poolBlocks  = (NN * 32 + 255) / 256;
    const int applyBlocks = (NN * (DD / 4) + 255) / 256;

    dim3 gemm1_grid((NN + 127) / 128, H2 / 128);
    dim3 gemm2_grid((NN + 127) / 128, DD / 128);
    dim3 gemmM_grid((GG + 127) / 128, DD / 128);

    for (int l = 0; l < LL; l++) {
        const float* hin = (l == 0) ? x : (const float*)hPtr;

        aggregate_kernel<<<aggBlocks, 256>>>(hin, eps + l);

        cudaMemsetAsync(statsPtr, 0, 2 * H2 * sizeof(float));
        gemm128_kernel<DD, H2, 2><<<gemm1_grid, 256>>>(
            aggPtr, W1 + (size_t)l * DD * H2, b1 + (size_t)l * H2, y1Ptr, NN);
        finalize_kernel<<<1, H2>>>(g1 + (size_t)l * H2, bt1 + (size_t)l * H2, NN, H2);

        cudaMemsetAsync(statsPtr, 0, 2 * H2 * sizeof(float));
        gemm128_kernel<H2, DD, 1><<<gemm2_grid, 256>>>(
            y1Ptr, W2 + (size_t)l * H2 * DD, b2 + (size_t)l * DD, y2Ptr, NN);
        finalize_kernel<<<1, DD>>>(g2 + (size_t)l * DD, bt2 + (size_t)l * DD, NN, DD);

        apply_bn_relu_kernel<<<applyBlocks, 256>>>(y2Ptr, hPtr, NN);
    }

    cudaMemsetAsync(gePtr, 0, (size_t)GG * DD * sizeof(float));
    pool_kernel<<<poolBlocks, 256>>>(hPtr, batch);

    cudaMemsetAsync(statsPtr, 0, 2 * H2 * sizeof(float));
    gemm128_kernel<DD, DD, 2><<<gemmM_grid, 256>>>(
        (const float*)gePtr, Wm1, bm1, gm1Ptr, GG);
    finalize_kernel<<<1, DD>>>(gm, btm, GG, DD);

    head_kernel<<<GG, DD>>>(gm1Ptr, Wm2, bm2, out);
}